// round 5
// baseline (speedup 1.0000x reference)
#include <cuda_runtime.h>
#include <math.h>

#define BATCH 16
#define HDIM 512
#define WDIM 512
#define NPIX (HDIM*WDIM)
#define KSEG 50
#define NITERS 10
#define NBLK (256*BATCH)              /* total blocks per k_assign launch */
#define FSCALE 16777216.0f            /* 2^24 fixed point */
#define INV_FSCALE (1.0/16777216.0)

/* global scratch: fixed-point per-segment accumulators and packed centers */
__device__ unsigned long long g_acc[BATCH][KSEG][6];
/* per cluster: [0]=(c0,c1,c2,c3)  [1]=(c4, c2sum, csy, csx) */
__device__ float4 g_cent[BATCH][KSEG][2];
__device__ unsigned int g_ticket;     /* last-block-done counter */

__device__ __forceinline__ float slic_ratio() {
    /* matches reference: COMPACTNESS / sqrt(N/K) computed in double, used as f32 */
    return (float)(10.0 / sqrt((double)NPIX / 50.0));
}

/* reference-shaped c2: rounded squares, sequential rounded adds (no FMA) */
__device__ __forceinline__ float c2_of(float c0, float c1, float c2v, float c3, float c4) {
    float s = __fmul_rn(c0, c0);
    s = __fadd_rn(s, __fmul_rn(c1, c1));
    s = __fadd_rn(s, __fmul_rn(c2v, c2v));
    s = __fadd_rn(s, __fmul_rn(c3, c3));
    s = __fadd_rn(s, __fmul_rn(c4, c4));
    return s;
}

/* ---------------- init: grid-sampled centers + zero accumulators ------------- */
__global__ void k_init(const float* __restrict__ x) {
    int b = blockIdx.x;
    int t = threadIdx.x;
    if (b == 0 && t == 0) g_ticket = 0u;
    if (t < KSEG) {
        /* n = ceil(sqrt(50)) = 8; centers at ((i+0.5)*512/8) = 32 + 64*i ; first 50 row-major */
        int ky = t >> 3, kx = t & 7;
        int cy = 32 + 64 * ky, cx = 32 + 64 * kx;
        const float* xb = x + (size_t)b * 3 * NPIX + (size_t)cy * WDIM + cx;
        float c0 = __ldg(xb), c1 = __ldg(xb + NPIX), c2v = __ldg(xb + 2 * NPIX);
        float r = slic_ratio();
        float c3 = __fmul_rn((float)cy, r), c4 = __fmul_rn((float)cx, r);
        g_cent[b][t][0] = make_float4(c0, c1, c2v, c3);
        g_cent[b][t][1] = make_float4(c4, c2_of(c0, c1, c2v, c3, c4), c3, c4);
    }
    for (int i = t; i < KSEG * 6; i += blockDim.x)
        ((unsigned long long*)g_acc[b])[i] = 0ull;
}

/* ---------------- assignment + fixed-point accumulation --------------------- */
__device__ __forceinline__ void flush_run(unsigned long long (*sacc)[6], int lab,
                                          float a0, float a1, float a2, float a3,
                                          float a4, int cnt) {
    atomicAdd(&sacc[lab][0], (unsigned long long)llrintf(a0 * FSCALE));
    atomicAdd(&sacc[lab][1], (unsigned long long)llrintf(a1 * FSCALE));
    atomicAdd(&sacc[lab][2], (unsigned long long)llrintf(a2 * FSCALE));
    atomicAdd(&sacc[lab][3], (unsigned long long)llrintf(a3 * FSCALE));
    atomicAdd(&sacc[lab][4], (unsigned long long)llrintf(a4 * FSCALE));
    atomicAdd(&sacc[lab][5], (unsigned long long)cnt);
}

/* mode: 1 = iteration pass (last block updates centers, resets accumulators)
         0 = final pass     (last block computes the 16 output scalars)        */
__global__ __launch_bounds__(256) void k_assign(const float* __restrict__ x,
                                                int mode, float* __restrict__ out) {
    const int b = blockIdx.y;
    const int tile = blockIdx.x;              /* 256 tiles of 32x32 per image */
    const int tile_x = (tile & 15) << 5;
    const int tile_y = (tile >> 4) << 5;
    const int t = threadIdx.x;

    __shared__ float4 s_cent[KSEG][2];
    __shared__ float  s_L[KSEG];
    __shared__ float  s_U[KSEG];
    __shared__ float4 s_cand[KSEG][2];
    __shared__ int    s_cidx[KSEG];
    __shared__ int    s_nc;
    __shared__ int    s_last;
    __shared__ unsigned long long s_acc[KSEG][6];

    const float r = slic_ratio();

    if (t < KSEG * 2) ((float4*)s_cent)[t] = __ldg(((const float4*)g_cent[b]) + t);
    for (int i = t; i < KSEG * 6; i += 256)
        ((unsigned long long*)s_acc)[i] = 0ull;
    __syncthreads();

    /* conservative spatial bounds for this tile (tile half-diag = 15.5*sqrt2) */
    if (t < KSEG) {
        float csy = s_cent[t][1].z, csx = s_cent[t][1].w;
        float tcy = ((float)tile_y + 15.5f) * r;
        float tcx = ((float)tile_x + 15.5f) * r;
        float RT  = r * 21.9205f;
        float dy = csy - tcy, dx = csx - tcx;
        float dist = sqrtf(dy * dy + dx * dx);
        float u = dist + RT;              s_U[t] = u * u;
        float l = fmaxf(dist - RT, 0.0f); s_L[t] = l * l;
    }
    __syncthreads();
    if (t == 0) {
        float mu = s_U[0];
        #pragma unroll
        for (int k = 1; k < KSEG; k++) mu = fminf(mu, s_U[k]);
        float thr = mu + 3.0f + 0.2f;     /* +3 = max color distance; +0.2 fp-noise margin */
        int nc = 0;
        for (int k = 0; k < KSEG; k++)
            if (s_L[k] <= thr) s_cidx[nc++] = k;   /* ascending k -> preserves first-min ties */
        s_nc = nc;
    }
    __syncthreads();
    const int nc = s_nc;
    if (t < nc * 2) { int j = t >> 1, h = t & 1; s_cand[j][h] = s_cent[s_cidx[j]][h]; }
    __syncthreads();

    /* each thread: 4 consecutive pixels of one row */
    const int tx = t & 7, ty = t >> 3;
    const int col = tile_x + (tx << 2);
    const int row = tile_y + ty;
    const float* xb = x + (size_t)b * 3 * NPIX + (size_t)row * WDIM + col;
    float4 fr = __ldg((const float4*)(xb));
    float4 fg = __ldg((const float4*)(xb + NPIX));
    float4 fb = __ldg((const float4*)(xb + 2 * NPIX));

    float f0[4] = { fr.x, fr.y, fr.z, fr.w };
    float f1[4] = { fg.x, fg.y, fg.z, fg.w };
    float f2c[4] = { fb.x, fb.y, fb.z, fb.w };
    const float f3 = __fmul_rn((float)row, r);
    float f4[4] = { __fmul_rn((float)(col),     r), __fmul_rn((float)(col + 1), r),
                    __fmul_rn((float)(col + 2), r), __fmul_rn((float)(col + 3), r) };

    /* f2 = sum(feats*feats): rounded squares, sequential rounded adds (ref shape) */
    float fsq[4];
    #pragma unroll
    for (int i = 0; i < 4; i++) {
        float s = __fmul_rn(f0[i], f0[i]);
        s = __fadd_rn(s, __fmul_rn(f1[i], f1[i]));
        s = __fadd_rn(s, __fmul_rn(f2c[i], f2c[i]));
        s = __fadd_rn(s, __fmul_rn(f3, f3));
        s = __fadd_rn(s, __fmul_rn(f4[i], f4[i]));
        fsq[i] = s;
    }

    float best[4] = { 3.0e38f, 3.0e38f, 3.0e38f, 3.0e38f };
    int   bi[4]   = { 0, 0, 0, 0 };

    for (int j = 0; j < nc; j++) {
        const float4 a  = s_cand[j][0];
        const float4 bv = s_cand[j][1];
        #pragma unroll
        for (int i = 0; i < 4; i++) {
            /* reference-shaped d: dot = k-ordered FMA chain; d = (f2 + c2) - 2*dot */
            float dot = __fmul_rn(f0[i], a.x);
            dot = fmaf(f1[i],  a.y,  dot);
            dot = fmaf(f2c[i], a.z,  dot);
            dot = fmaf(f3,     a.w,  dot);
            dot = fmaf(f4[i],  bv.x, dot);
            float tt = __fadd_rn(fsq[i], bv.y);
            float d  = __fadd_rn(tt, -2.0f * dot);
            if (d < best[i]) { best[i] = d; bi[i] = j; }
        }
    }
    int lab[4];
    #pragma unroll
    for (int i = 0; i < 4; i++) lab[i] = s_cidx[bi[i]];

    /* run-length fold (pixels are spatially adjacent -> mostly one segment) */
    {
        float a0 = f0[0], a1 = f1[0], a2 = f2c[0], a3 = f3, a4 = f4[0];
        int cnt = 1, cur = lab[0];
        #pragma unroll
        for (int i = 1; i < 4; i++) {
            if (lab[i] == cur) {
                a0 += f0[i]; a1 += f1[i]; a2 += f2c[i]; a3 += f3; a4 += f4[i]; cnt++;
            } else {
                flush_run(s_acc, cur, a0, a1, a2, a3, a4, cnt);
                a0 = f0[i]; a1 = f1[i]; a2 = f2c[i]; a3 = f3; a4 = f4[i];
                cnt = 1; cur = lab[i];
            }
        }
        flush_run(s_acc, cur, a0, a1, a2, a3, a4, cnt);
    }
    __syncthreads();

    /* block -> global: only candidate segments can be non-empty */
    for (int i = t; i < nc * 6; i += 256) {
        int j = i / 6, d = i - j * 6;
        int k = s_cidx[j];
        unsigned long long v = s_acc[k][d];
        if (v) atomicAdd(&g_acc[b][k][d], v);
    }

    /* ---- last-block-done: center update (mode=1) or final output (mode=0) ---- */
    __threadfence();
    __syncthreads();
    if (t == 0) {
        unsigned int old = atomicAdd(&g_ticket, 1u);
        s_last = (old == (unsigned int)(NBLK - 1));
    }
    __syncthreads();
    if (!s_last) return;
    if (t == 0) g_ticket = 0u;            /* reset for next launch / replay */

    if (mode == 1) {
        for (int i = t; i < BATCH * KSEG; i += 256) {
            int bb = i / KSEG, k = i - bb * KSEG;
            unsigned long long* a = g_acc[bb][k];
            /* atomicExch: reads the fully-accumulated value and resets to 0 */
            unsigned long long s0 = atomicExch(&a[0], 0ull);
            unsigned long long s1 = atomicExch(&a[1], 0ull);
            unsigned long long s2 = atomicExch(&a[2], 0ull);
            unsigned long long s3 = atomicExch(&a[3], 0ull);
            unsigned long long s4 = atomicExch(&a[4], 0ull);
            unsigned long long cn = atomicExch(&a[5], 0ull);
            double cm = (cn > 0) ? (double)cn : 1.0;
            double inv = INV_FSCALE / cm;
            float c0 = (float)((double)s0 * inv);
            float c1 = (float)((double)s1 * inv);
            float c2v = (float)((double)s2 * inv);
            float c3 = (float)((double)s3 * inv);
            float c4 = (float)((double)s4 * inv);
            g_cent[bb][k][0] = make_float4(c0, c1, c2v, c3);
            g_cent[bb][k][1] = make_float4(c4, c2_of(c0, c1, c2v, c3, c4), c3, c4);
        }
    } else {
        /* final output: weighted channel means -> colorfulness scalar per image */
        __shared__ double s_sum[BATCH][3];
        if (t < BATCH * 3) {
            int bb = t / 3, ch = t - bb * 3;
            double s = 0.0;
            for (int k = 0; k < KSEG; k++) {        /* fixed order: deterministic */
                unsigned long long cn = g_acc[bb][k][5];
                double cm = (cn > 0) ? (double)cn : 1.0;
                s += (double)g_acc[bb][k][ch] * (INV_FSCALE / cm);
            }
            s_sum[bb][ch] = s;
        }
        __syncthreads();
        if (t < BATCH) {
            float mrf = (float)(s_sum[t][0] / (double)NPIX);
            float mgf = (float)(s_sum[t][1] / (double)NPIX);
            float mbf = (float)(s_sum[t][2] / (double)NPIX);
            float Drg = __fmul_rn(__fadd_rn(mrf, -mgf), __fadd_rn(mrf, -mgf));
            float Drb = __fmul_rn(__fadd_rn(mrf, -mbf), __fadd_rn(mrf, -mbf));
            float Dgb = __fmul_rn(__fadd_rn(mbf, -mgf), __fadd_rn(mbf, -mgf));
            float ssum = __fadd_rn(__fadd_rn(__fmul_rn(Drg, Drg), __fmul_rn(Drb, Drb)),
                                   __fmul_rn(Dgb, Dgb));
            out[t] = sqrtf(ssum);
        }
    }
}

/* ---------------- launch ---------------------------------------------------- */
extern "C" void kernel_launch(void* const* d_in, const int* in_sizes, int n_in,
                              void* d_out, int out_size) {
    (void)in_sizes; (void)n_in; (void)out_size;
    const float* x = (const float*)d_in[0];
    float* out = (float*)d_out;

    k_init<<<BATCH, 64>>>(x);
    dim3 grid(256, BATCH);
    for (int it = 0; it < NITERS; ++it)
        k_assign<<<grid, 256>>>(x, 1, out);   /* center update fused into last block */
    k_assign<<<grid, 256>>>(x, 0, out);       /* final pass computes the output */
}

// round 6
// speedup vs baseline: 11.0249x; 11.0249x over previous
#include <cuda_runtime.h>
#include <math.h>

#define BATCH 16
#define HDIM 512
#define WDIM 512
#define NPIX (HDIM*WDIM)
#define KSEG 50
#define NITERS 10
#define NBLK (256*BATCH)              /* total blocks per k_assign launch */
#define FSCALE 16777216.0f            /* 2^24 fixed point */
#define INV_FSCALE (1.0/16777216.0)

/* global scratch: fixed-point per-segment accumulators and packed centers */
__device__ unsigned long long g_acc[BATCH][KSEG][6];
/* per cluster: [0]=(c0,c1,c2,c3)  [1]=(c4, c2sum, csy, csx) */
__device__ float4 g_cent[BATCH][KSEG][2];
__device__ unsigned int g_ticket;     /* last-block-done counter */

__device__ __forceinline__ float slic_ratio() {
    /* matches reference: COMPACTNESS / sqrt(N/K) computed in double, used as f32 */
    return (float)(10.0 / sqrt((double)NPIX / 50.0));
}

/* reference-shaped c2: rounded squares, sequential rounded adds (no FMA) */
__device__ __forceinline__ float c2_of(float c0, float c1, float c2v, float c3, float c4) {
    float s = __fmul_rn(c0, c0);
    s = __fadd_rn(s, __fmul_rn(c1, c1));
    s = __fadd_rn(s, __fmul_rn(c2v, c2v));
    s = __fadd_rn(s, __fmul_rn(c3, c3));
    s = __fadd_rn(s, __fmul_rn(c4, c4));
    return s;
}

/* ---------------- init: grid-sampled centers + zero accumulators ------------- */
__global__ void k_init(const float* __restrict__ x) {
    int b = blockIdx.x;
    int t = threadIdx.x;
    if (b == 0 && t == 0) g_ticket = 0u;
    if (t < KSEG) {
        int ky = t >> 3, kx = t & 7;
        int cy = 32 + 64 * ky, cx = 32 + 64 * kx;
        const float* xb = x + (size_t)b * 3 * NPIX + (size_t)cy * WDIM + cx;
        float c0 = __ldg(xb), c1 = __ldg(xb + NPIX), c2v = __ldg(xb + 2 * NPIX);
        float r = slic_ratio();
        float c3 = __fmul_rn((float)cy, r), c4 = __fmul_rn((float)cx, r);
        g_cent[b][t][0] = make_float4(c0, c1, c2v, c3);
        g_cent[b][t][1] = make_float4(c4, c2_of(c0, c1, c2v, c3, c4), c3, c4);
    }
    for (int i = t; i < KSEG * 6; i += blockDim.x)
        ((unsigned long long*)g_acc[b])[i] = 0ull;
}

/* mode: 1 = iteration pass (last block updates centers, resets accumulators)
         0 = final pass     (last block computes the 16 output scalars)        */
__global__ __launch_bounds__(256) void k_assign(const float* __restrict__ x,
                                                int mode, float* __restrict__ out) {
    const int b = blockIdx.y;
    const int tile = blockIdx.x;              /* 256 tiles of 32x32 per image */
    const int tile_x = (tile & 15) << 5;
    const int tile_y = (tile >> 4) << 5;
    const int t = threadIdx.x;
    const int lane = t & 31;
    const int w = t >> 5;

    __shared__ float4 s_cent[KSEG][2];
    __shared__ float  s_L[KSEG];
    __shared__ float  s_U[KSEG];
    __shared__ float4 s_cand[KSEG][2];
    __shared__ int    s_cidx[KSEG];
    __shared__ int    s_nc;
    __shared__ int    s_last;

    const float r = slic_ratio();

    if (t < KSEG * 2) ((float4*)s_cent)[t] = __ldg(((const float4*)g_cent[b]) + t);
    __syncthreads();

    /* tile-level conservative spatial bounds (tile half-diag = 15.5*sqrt2) */
    if (t < KSEG) {
        float csy = s_cent[t][1].z, csx = s_cent[t][1].w;
        float tcy = ((float)tile_y + 15.5f) * r;
        float tcx = ((float)tile_x + 15.5f) * r;
        float RT  = r * 21.9205f;
        float dy = csy - tcy, dx = csx - tcx;
        float dist = sqrtf(dy * dy + dx * dx);
        float u = dist + RT;              s_U[t] = u * u;
        float l = fmaxf(dist - RT, 0.0f); s_L[t] = l * l;
    }
    __syncthreads();
    if (t == 0) {
        float mu = s_U[0];
        #pragma unroll
        for (int k = 1; k < KSEG; k++) mu = fminf(mu, s_U[k]);
        float thr = mu + 3.0f + 0.2f;     /* +3 = max color dist^2; +0.2 fp margin */
        int nc = 0;
        for (int k = 0; k < KSEG; k++)
            if (s_L[k] <= thr) s_cidx[nc++] = k;   /* ascending k: first-min ties */
        s_nc = nc;
    }
    __syncthreads();
    const int nc = s_nc;
    if (t < nc * 2) { int j = t >> 1, h = t & 1; s_cand[j][h] = s_cent[s_cidx[j]][h]; }
    __syncthreads();

    /* ---- warp-level re-prune: warp box = rows [tile_y+4w, +3] x 32 cols ---- */
    float wcy = ((float)(tile_y + (w << 2)) + 1.5f) * r;
    float wcx = ((float)tile_x + 15.5f) * r;
    const float RTw = r * 15.5725f;       /* sqrt(15.5^2 + 1.5^2) rounded up */
    float U0 = 3.0e38f, U1 = 3.0e38f, L0 = 3.0e38f, L1v = 3.0e38f;
    if (lane < nc) {
        float dy = s_cand[lane][1].z - wcy, dx = s_cand[lane][1].w - wcx;
        float dist = sqrtf(dy * dy + dx * dx);
        float u = dist + RTw;              U0 = u * u;
        float l = fmaxf(dist - RTw, 0.0f); L0 = l * l;
    }
    if (lane + 32 < nc) {
        float dy = s_cand[lane + 32][1].z - wcy, dx = s_cand[lane + 32][1].w - wcx;
        float dist = sqrtf(dy * dy + dx * dx);
        float u = dist + RTw;              U1 = u * u;
        float l = fmaxf(dist - RTw, 0.0f); L1v = l * l;
    }
    float um = fminf(U0, U1);
    #pragma unroll
    for (int o = 16; o; o >>= 1) um = fminf(um, __shfl_xor_sync(0xffffffffu, um, o));
    float thrw = um + 3.2f;
    unsigned int mlo = __ballot_sync(0xffffffffu, (lane      < nc) && (L0  <= thrw));
    unsigned int mhi = __ballot_sync(0xffffffffu, (lane + 32 < nc) && (L1v <= thrw));
    unsigned long long wmask = (unsigned long long)mlo | ((unsigned long long)mhi << 32);

    /* ---- pixels: 4 consecutive per thread ---- */
    const int tx = t & 7, ty = t >> 3;
    const int col = tile_x + (tx << 2);
    const int row = tile_y + ty;
    const float* xb = x + (size_t)b * 3 * NPIX + (size_t)row * WDIM + col;
    float4 fr = __ldg((const float4*)(xb));
    float4 fg = __ldg((const float4*)(xb + NPIX));
    float4 fb = __ldg((const float4*)(xb + 2 * NPIX));

    float f0[4]  = { fr.x, fr.y, fr.z, fr.w };
    float f1[4]  = { fg.x, fg.y, fg.z, fg.w };
    float f2c[4] = { fb.x, fb.y, fb.z, fb.w };
    const float f3 = __fmul_rn((float)row, r);
    float f4[4] = { __fmul_rn((float)(col),     r), __fmul_rn((float)(col + 1), r),
                    __fmul_rn((float)(col + 2), r), __fmul_rn((float)(col + 3), r) };

    /* f2 = sum(feats*feats): rounded squares, sequential rounded adds (ref shape) */
    float fsq[4];
    #pragma unroll
    for (int i = 0; i < 4; i++) {
        float s = __fmul_rn(f0[i], f0[i]);
        s = __fadd_rn(s, __fmul_rn(f1[i], f1[i]));
        s = __fadd_rn(s, __fmul_rn(f2c[i], f2c[i]));
        s = __fadd_rn(s, __fmul_rn(f3, f3));
        s = __fadd_rn(s, __fmul_rn(f4[i], f4[i]));
        fsq[i] = s;
    }

    float best[4] = { 3.0e38f, 3.0e38f, 3.0e38f, 3.0e38f };
    int   bi[4]   = { 0, 0, 0, 0 };   /* candidate slot index */

    unsigned long long m = wmask;
    while (m) {
        int j = __ffsll(m) - 1; m &= m - 1;
        const float4 a  = s_cand[j][0];
        const float4 bv = s_cand[j][1];
        #pragma unroll
        for (int i = 0; i < 4; i++) {
            /* reference-shaped d: dot = k-ordered FMA chain; d = (f2 + c2) - 2*dot */
            float dot = __fmul_rn(f0[i], a.x);
            dot = fmaf(f1[i],  a.y,  dot);
            dot = fmaf(f2c[i], a.z,  dot);
            dot = fmaf(f3,     a.w,  dot);
            dot = fmaf(f4[i],  bv.x, dot);
            float tt = __fadd_rn(fsq[i], bv.y);
            float d  = __fadd_rn(tt, -2.0f * dot);
            if (d < best[i]) { best[i] = d; bi[i] = j; }
        }
    }

    /* ---- warp-aggregated accumulation: butterfly reduce, lane0 -> global ---- */
    unsigned long long guard = 0ull;
    m = wmask;
    while (m) {
        int j = __ffsll(m) - 1; m &= m - 1;
        bool has = (bi[0] == j) | (bi[1] == j) | (bi[2] == j) | (bi[3] == j);
        unsigned int bal = __ballot_sync(0xffffffffu, has);
        if (!bal) continue;
        float p0 = 0.f, p1 = 0.f, p2 = 0.f, p3 = 0.f, p4 = 0.f, pc = 0.f;
        #pragma unroll
        for (int i = 0; i < 4; i++) {
            if (bi[i] == j) { p0 += f0[i]; p1 += f1[i]; p2 += f2c[i]; p3 += f3; p4 += f4[i]; pc += 1.0f; }
        }
        #pragma unroll
        for (int o = 16; o; o >>= 1) {
            p0 += __shfl_xor_sync(0xffffffffu, p0, o);
            p1 += __shfl_xor_sync(0xffffffffu, p1, o);
            p2 += __shfl_xor_sync(0xffffffffu, p2, o);
            p3 += __shfl_xor_sync(0xffffffffu, p3, o);
            p4 += __shfl_xor_sync(0xffffffffu, p4, o);
            pc += __shfl_xor_sync(0xffffffffu, pc, o);
        }
        if (lane == 0) {
            int k = s_cidx[j];
            unsigned long long* a8 = g_acc[b][k];
            /* returns consumed via guard: forces completion at L2 before barrier */
            guard |= atomicAdd(&a8[0], (unsigned long long)llrintf(p0 * FSCALE));
            guard |= atomicAdd(&a8[1], (unsigned long long)llrintf(p1 * FSCALE));
            guard |= atomicAdd(&a8[2], (unsigned long long)llrintf(p2 * FSCALE));
            guard |= atomicAdd(&a8[3], (unsigned long long)llrintf(p3 * FSCALE));
            guard |= atomicAdd(&a8[4], (unsigned long long)llrintf(p4 * FSCALE));
            guard |= atomicAdd(&a8[5], (unsigned long long)llrintf(pc));
        }
    }
    /* sums stay < 2^63 so bit63 is never set; branch forces atomics performed */
    if (guard & 0x8000000000000000ull) atomicExch(&g_ticket, 1234567u);
    __syncthreads();

    /* ---- last-block-done ---- */
    if (t == 0) {
        unsigned int old = atomicAdd(&g_ticket, 1u);
        s_last = (old == (unsigned int)(NBLK - 1));
    }
    __syncthreads();
    if (!s_last) return;
    if (t == 0) atomicExch(&g_ticket, 0u);     /* reset for next launch / replay */

    if (mode == 1) {
        for (int i = t; i < BATCH * KSEG; i += 256) {
            int bb = i / KSEG, k = i - bb * KSEG;
            unsigned long long* a = g_acc[bb][k];
            unsigned long long s0 = atomicExch(&a[0], 0ull);
            unsigned long long s1 = atomicExch(&a[1], 0ull);
            unsigned long long s2 = atomicExch(&a[2], 0ull);
            unsigned long long s3 = atomicExch(&a[3], 0ull);
            unsigned long long s4 = atomicExch(&a[4], 0ull);
            unsigned long long cn = atomicExch(&a[5], 0ull);
            double cm = (cn > 0) ? (double)cn : 1.0;
            double inv = INV_FSCALE / cm;
            float c0 = (float)((double)s0 * inv);
            float c1 = (float)((double)s1 * inv);
            float c2v = (float)((double)s2 * inv);
            float c3 = (float)((double)s3 * inv);
            float c4 = (float)((double)s4 * inv);
            g_cent[bb][k][0] = make_float4(c0, c1, c2v, c3);
            g_cent[bb][k][1] = make_float4(c4, c2_of(c0, c1, c2v, c3, c4), c3, c4);
        }
    } else {
        /* final output: weighted channel means -> colorfulness scalar per image */
        __shared__ double s_sum[BATCH][3];
        if (t < BATCH * 3) {
            int bb = t / 3, ch = t - bb * 3;
            double s = 0.0;
            for (int k = 0; k < KSEG; k++) {        /* fixed order: deterministic */
                unsigned long long cn = __ldcg(&g_acc[bb][k][5]);
                double cm = (cn > 0) ? (double)cn : 1.0;
                s += (double)__ldcg(&g_acc[bb][k][ch]) * (INV_FSCALE / cm);
            }
            s_sum[bb][ch] = s;
        }
        __syncthreads();
        if (t < BATCH) {
            float mrf = (float)(s_sum[t][0] / (double)NPIX);
            float mgf = (float)(s_sum[t][1] / (double)NPIX);
            float mbf = (float)(s_sum[t][2] / (double)NPIX);
            float Drg = __fmul_rn(__fadd_rn(mrf, -mgf), __fadd_rn(mrf, -mgf));
            float Drb = __fmul_rn(__fadd_rn(mrf, -mbf), __fadd_rn(mrf, -mbf));
            float Dgb = __fmul_rn(__fadd_rn(mbf, -mgf), __fadd_rn(mbf, -mgf));
            float ssum = __fadd_rn(__fadd_rn(__fmul_rn(Drg, Drg), __fmul_rn(Drb, Drb)),
                                   __fmul_rn(Dgb, Dgb));
            out[t] = sqrtf(ssum);
        }
    }
}

/* ---------------- launch ---------------------------------------------------- */
extern "C" void kernel_launch(void* const* d_in, const int* in_sizes, int n_in,
                              void* d_out, int out_size) {
    (void)in_sizes; (void)n_in; (void)out_size;
    const float* x = (const float*)d_in[0];
    float* out = (float*)d_out;

    k_init<<<BATCH, 64>>>(x);
    dim3 grid(256, BATCH);
    for (int it = 0; it < NITERS; ++it)
        k_assign<<<grid, 256>>>(x, 1, out);   /* center update fused into last block */
    k_assign<<<grid, 256>>>(x, 0, out);       /* final pass computes the output */
}

// round 13
// speedup vs baseline: 11.9318x; 1.0823x over previous
#include <cuda_runtime.h>
#include <math.h>

#define BATCH 16
#define HDIM 512
#define WDIM 512
#define NPIX (HDIM*WDIM)
#define KSEG 50
#define NITERS 10
#define NBLK (128*BATCH)              /* total blocks per k_assign launch */
#define FSCALE_W 8388608.0f           /* 2^23: per-thread fixed point for redux */
#define INV_FSCALE (1.0/16777216.0)   /* g_acc color units stay 2^-24 */

/* global scratch: per-segment accumulators and packed centers
   g_acc[b][k]: [0..2] color sums in 2^-24 fixed point, [3] raw row sum,
                [4] raw col sum, [5] count                                   */
__device__ unsigned long long g_acc[BATCH][KSEG][6];
/* per cluster: [0]=(c0,c1,c2,c3)  [1]=(c4, c2sum, csy, csx) */
__device__ float4 g_cent[BATCH][KSEG][2];
__device__ unsigned int g_ticket;     /* last-block-done counter */

__device__ __forceinline__ float slic_ratio() {
    return (float)(10.0 / sqrt((double)NPIX / 50.0));
}

/* reference-shaped c2: rounded squares, sequential rounded adds (no FMA) */
__device__ __forceinline__ float c2_of(float c0, float c1, float c2v, float c3, float c4) {
    float s = __fmul_rn(c0, c0);
    s = __fadd_rn(s, __fmul_rn(c1, c1));
    s = __fadd_rn(s, __fmul_rn(c2v, c2v));
    s = __fadd_rn(s, __fmul_rn(c3, c3));
    s = __fadd_rn(s, __fmul_rn(c4, c4));
    return s;
}

/* ---------------- init ------------------------------------------------------ */
__global__ void k_init(const float* __restrict__ x) {
    int b = blockIdx.x;
    int t = threadIdx.x;
    if (b == 0 && t == 0) g_ticket = 0u;
    if (t < KSEG) {
        int ky = t >> 3, kx = t & 7;
        int cy = 32 + 64 * ky, cx = 32 + 64 * kx;
        const float* xb = x + (size_t)b * 3 * NPIX + (size_t)cy * WDIM + cx;
        float c0 = __ldg(xb), c1 = __ldg(xb + NPIX), c2v = __ldg(xb + 2 * NPIX);
        float r = slic_ratio();
        float c3 = __fmul_rn((float)cy, r), c4 = __fmul_rn((float)cx, r);
        g_cent[b][t][0] = make_float4(c0, c1, c2v, c3);
        g_cent[b][t][1] = make_float4(c4, c2_of(c0, c1, c2v, c3, c4), c3, c4);
    }
    for (int i = t; i < KSEG * 6; i += blockDim.x)
        ((unsigned long long*)g_acc[b])[i] = 0ull;
}

/* mode: 1 = iteration pass (last block updates centers + resets accumulators)
         0 = final pass     (last block computes the 16 output scalars)        */
__global__ __launch_bounds__(256) void k_assign(const float* __restrict__ x,
                                                int mode, float* __restrict__ out) {
    const int b = blockIdx.y;
    const int tile = blockIdx.x;              /* 128 tiles of 32(w)x64(h) per image */
    const int tile_x = (tile & 15) << 5;
    const int tile_y = (tile >> 4) << 6;
    const int t = threadIdx.x;
    const int lane = t & 31;
    const int w = t >> 5;

    __shared__ float4 s_cent[KSEG][2];
    __shared__ float  s_L[KSEG];
    __shared__ float  s_U[KSEG];
    __shared__ float4 s_cand[KSEG][2];
    __shared__ int    s_cidx[KSEG];
    __shared__ int    s_nc;
    __shared__ int    s_last;

    const float r = slic_ratio();

    if (t < KSEG * 2) ((float4*)s_cent)[t] = __ldg(((const float4*)g_cent[b]) + t);
    __syncthreads();

    /* tile-level conservative spatial bounds (half-diag sqrt(15.5^2+31.5^2)=35.11) */
    if (t < KSEG) {
        float csy = s_cent[t][1].z, csx = s_cent[t][1].w;
        float tcy = ((float)tile_y + 31.5f) * r;
        float tcx = ((float)tile_x + 15.5f) * r;
        float RT  = r * 35.2f;
        float dy = csy - tcy, dx = csx - tcx;
        float dist = sqrtf(dy * dy + dx * dx);
        float u = dist + RT;              s_U[t] = u * u;
        float l = fmaxf(dist - RT, 0.0f); s_L[t] = l * l;
    }
    __syncthreads();
    if (t == 0) {
        float mu = s_U[0];
        #pragma unroll
        for (int k = 1; k < KSEG; k++) mu = fminf(mu, s_U[k]);
        float thr = mu + 3.0f + 0.2f;     /* +3 = max color dist^2; +0.2 fp margin */
        int nc = 0;
        for (int k = 0; k < KSEG; k++)
            if (s_L[k] <= thr) s_cidx[nc++] = k;   /* ascending k: first-min ties */
        s_nc = nc;
    }
    __syncthreads();
    const int nc = s_nc;
    if (t < nc * 2) { int j = t >> 1, h = t & 1; s_cand[j][h] = s_cent[s_cidx[j]][h]; }
    __syncthreads();

    /* ---- warp-level re-prune: warp box = rows [tile_y+8w, +7] x 32 cols ---- */
    float wcy = ((float)(tile_y + (w << 3)) + 3.5f) * r;
    float wcx = ((float)tile_x + 15.5f) * r;
    const float RTw = r * 15.90f;         /* sqrt(15.5^2 + 3.5^2) = 15.89, rounded up */
    float U0 = 3.0e38f, U1 = 3.0e38f, L0 = 3.0e38f, L1v = 3.0e38f;
    if (lane < nc) {
        float dy = s_cand[lane][1].z - wcy, dx = s_cand[lane][1].w - wcx;
        float dist = sqrtf(dy * dy + dx * dx);
        float u = dist + RTw;              U0 = u * u;
        float l = fmaxf(dist - RTw, 0.0f); L0 = l * l;
    }
    if (lane + 32 < nc) {
        float dy = s_cand[lane + 32][1].z - wcy, dx = s_cand[lane + 32][1].w - wcx;
        float dist = sqrtf(dy * dy + dx * dx);
        float u = dist + RTw;              U1 = u * u;
        float l = fmaxf(dist - RTw, 0.0f); L1v = l * l;
    }
    float um = fminf(U0, U1);
    #pragma unroll
    for (int o = 16; o; o >>= 1) um = fminf(um, __shfl_xor_sync(0xffffffffu, um, o));
    float thrw = um + 3.2f;
    unsigned int mlo = __ballot_sync(0xffffffffu, (lane      < nc) && (L0  <= thrw));
    unsigned int mhi = __ballot_sync(0xffffffffu, (lane + 32 < nc) && (L1v <= thrw));
    unsigned long long wmask = (unsigned long long)mlo | ((unsigned long long)mhi << 32);

    /* ---- pixels: 8 per thread = 2 rows x 4 consecutive cols ---- */
    const int col  = tile_x + ((lane & 7) << 2);
    const int row0 = tile_y + (w << 3) + ((lane >> 3) << 1);
    const float* xb = x + (size_t)b * 3 * NPIX + (size_t)row0 * WDIM + col;
    float4 fr0 = __ldg((const float4*)(xb));
    float4 fr1 = __ldg((const float4*)(xb + WDIM));
    float4 fg0 = __ldg((const float4*)(xb + NPIX));
    float4 fg1 = __ldg((const float4*)(xb + NPIX + WDIM));
    float4 fb0 = __ldg((const float4*)(xb + 2 * NPIX));
    float4 fb1 = __ldg((const float4*)(xb + 2 * NPIX + WDIM));

    float f0[8]  = { fr0.x, fr0.y, fr0.z, fr0.w, fr1.x, fr1.y, fr1.z, fr1.w };
    float f1[8]  = { fg0.x, fg0.y, fg0.z, fg0.w, fg1.x, fg1.y, fg1.z, fg1.w };
    float f2c[8] = { fb0.x, fb0.y, fb0.z, fb0.w, fb1.x, fb1.y, fb1.z, fb1.w };
    const float f3a = __fmul_rn((float)row0,       r);
    const float f3b = __fmul_rn((float)(row0 + 1), r);
    float f4[4] = { __fmul_rn((float)(col),     r), __fmul_rn((float)(col + 1), r),
                    __fmul_rn((float)(col + 2), r), __fmul_rn((float)(col + 3), r) };

    /* f2 = sum(feats*feats): rounded squares, sequential rounded adds (ref shape) */
    float fsq[8];
    #pragma unroll
    for (int i = 0; i < 8; i++) {
        float f3v = (i < 4) ? f3a : f3b;
        float s = __fmul_rn(f0[i], f0[i]);
        s = __fadd_rn(s, __fmul_rn(f1[i], f1[i]));
        s = __fadd_rn(s, __fmul_rn(f2c[i], f2c[i]));
        s = __fadd_rn(s, __fmul_rn(f3v, f3v));
        s = __fadd_rn(s, __fmul_rn(f4[i & 3], f4[i & 3]));
        fsq[i] = s;
    }

    float best[8];
    int   bi[8];
    #pragma unroll
    for (int i = 0; i < 8; i++) { best[i] = 3.0e38f; bi[i] = 0; }

    unsigned long long m = wmask;
    while (m) {
        int j = __ffsll(m) - 1; m &= m - 1;
        const float4 a  = s_cand[j][0];
        const float4 bv = s_cand[j][1];
        #pragma unroll
        for (int i = 0; i < 8; i++) {
            /* reference-shaped d: dot = k-ordered FMA chain; d = (f2 + c2) - 2*dot */
            float dot = __fmul_rn(f0[i], a.x);
            dot = fmaf(f1[i],  a.y,  dot);
            dot = fmaf(f2c[i], a.z,  dot);
            dot = fmaf((i < 4) ? f3a : f3b, a.w, dot);
            dot = fmaf(f4[i & 3], bv.x, dot);
            float tt = __fadd_rn(fsq[i], bv.y);
            float d  = __fadd_rn(tt, -2.0f * dot);
            if (d < best[i]) { best[i] = d; bi[i] = j; }
        }
    }

    /* ---- warp-aggregated accumulation via REDUX.SYNC ---- */
    unsigned long long guard = 0ull;
    m = wmask;
    while (m) {
        int j = __ffsll(m) - 1; m &= m - 1;
        bool has = false;
        #pragma unroll
        for (int i = 0; i < 8; i++) has |= (bi[i] == j);
        unsigned int bal = __ballot_sync(0xffffffffu, has);
        if (!bal) continue;
        float p0 = 0.f, p1 = 0.f, p2 = 0.f;
        int prow = 0, pcol = 0, pcnt = 0;
        #pragma unroll
        for (int i = 0; i < 8; i++) {
            if (bi[i] == j) {
                p0 += f0[i]; p1 += f1[i]; p2 += f2c[i];
                prow += row0 + (i >> 2); pcol += col + (i & 3); pcnt++;
            }
        }
        unsigned int u0 = __reduce_add_sync(0xffffffffu, (unsigned int)llrintf(p0 * FSCALE_W));
        unsigned int u1 = __reduce_add_sync(0xffffffffu, (unsigned int)llrintf(p1 * FSCALE_W));
        unsigned int u2 = __reduce_add_sync(0xffffffffu, (unsigned int)llrintf(p2 * FSCALE_W));
        unsigned int ur = __reduce_add_sync(0xffffffffu, (unsigned int)prow);
        unsigned int uc = __reduce_add_sync(0xffffffffu, (unsigned int)pcol);
        unsigned int un = __reduce_add_sync(0xffffffffu, (unsigned int)pcnt);
        if (lane == 0) {
            int k = s_cidx[j];
            unsigned long long* a8 = g_acc[b][k];
            /* returns consumed via guard: forces completion at L2 before barrier */
            guard |= atomicAdd(&a8[0], ((unsigned long long)u0) << 1);  /* -> 2^-24 units */
            guard |= atomicAdd(&a8[1], ((unsigned long long)u1) << 1);
            guard |= atomicAdd(&a8[2], ((unsigned long long)u2) << 1);
            guard |= atomicAdd(&a8[3], (unsigned long long)ur);          /* raw row sum */
            guard |= atomicAdd(&a8[4], (unsigned long long)uc);          /* raw col sum */
            guard |= atomicAdd(&a8[5], (unsigned long long)un);          /* count */
        }
    }
    /* sums stay < 2^63 so bit63 is never set; branch forces atomics performed */
    if (guard & 0x8000000000000000ull) atomicExch(&g_ticket, 1234567u);
    __syncthreads();

    /* ---- last-block-done ---- */
    if (t == 0) {
        unsigned int old = atomicAdd(&g_ticket, 1u);
        s_last = (old == (unsigned int)(NBLK - 1));
    }
    __syncthreads();
    if (!s_last) return;
    if (t == 0) atomicExch(&g_ticket, 0u);     /* reset for next launch / replay */

    if (mode == 1) {
        for (int i = t; i < BATCH * KSEG; i += 256) {
            int bb = i / KSEG, k = i - bb * KSEG;
            unsigned long long* a = g_acc[bb][k];
            unsigned long long s0 = atomicExch(&a[0], 0ull);
            unsigned long long s1 = atomicExch(&a[1], 0ull);
            unsigned long long s2 = atomicExch(&a[2], 0ull);
            unsigned long long s3 = atomicExch(&a[3], 0ull);
            unsigned long long s4 = atomicExch(&a[4], 0ull);
            unsigned long long cn = atomicExch(&a[5], 0ull);
            double cm = (cn > 0) ? (double)cn : 1.0;
            double inv = INV_FSCALE / cm;
            float c0 = (float)((double)s0 * inv);
            float c1 = (float)((double)s1 * inv);
            float c2v = (float)((double)s2 * inv);
            float c3 = (float)((double)s3 * (double)r / cm);   /* exact int sum * r */
            float c4 = (float)((double)s4 * (double)r / cm);
            g_cent[bb][k][0] = make_float4(c0, c1, c2v, c3);
            g_cent[bb][k][1] = make_float4(c4, c2_of(c0, c1, c2v, c3, c4), c3, c4);
        }
    } else {
        /* final output: weighted channel means -> colorfulness scalar per image */
        __shared__ double s_sum[BATCH][3];
        if (t < BATCH * 3) {
            int bb = t / 3, ch = t - bb * 3;
            double s = 0.0;
            for (int k = 0; k < KSEG; k++) {        /* fixed order: deterministic */
                unsigned long long cn = __ldcg(&g_acc[bb][k][5]);
                double cm = (cn > 0) ? (double)cn : 1.0;
                s += (double)__ldcg(&g_acc[bb][k][ch]) * (INV_FSCALE / cm);
            }
            s_sum[bb][ch] = s;
        }
        __syncthreads();
        if (t < BATCH) {
            float mrf = (float)(s_sum[t][0] / (double)NPIX);
            float mgf = (float)(s_sum[t][1] / (double)NPIX);
            float mbf = (float)(s_sum[t][2] / (double)NPIX);
            float Drg = __fmul_rn(__fadd_rn(mrf, -mgf), __fadd_rn(mrf, -mgf));
            float Drb = __fmul_rn(__fadd_rn(mrf, -mbf), __fadd_rn(mrf, -mbf));
            float Dgb = __fmul_rn(__fadd_rn(mbf, -mgf), __fadd_rn(mbf, -mgf));
            float ssum = __fadd_rn(__fadd_rn(__fmul_rn(Drg, Drg), __fmul_rn(Drb, Drb)),
                                   __fmul_rn(Dgb, Dgb));
            out[t] = sqrtf(ssum);
        }
    }
}

/* ---------------- launch ---------------------------------------------------- */
extern "C" void kernel_launch(void* const* d_in, const int* in_sizes, int n_in,
                              void* d_out, int out_size) {
    (void)in_sizes; (void)n_in; (void)out_size;
    const float* x = (const float*)d_in[0];
    float* out = (float*)d_out;

    k_init<<<BATCH, 64>>>(x);
    dim3 grid(128, BATCH);
    for (int it = 0; it < NITERS; ++it)
        k_assign<<<grid, 256>>>(x, 1, out);   /* center update fused into last block */
    k_assign<<<grid, 256>>>(x, 0, out);       /* final pass computes the output */
}